// round 13
// baseline (speedup 1.0000x reference)
#include <cuda_runtime.h>
#include <cuda_bf16.h>
#include <cstdint>
#include <math.h>

#define Dm   768
#define Tt   4096
#define NB   4
#define MTOT (NB * Tt)   // 16384

typedef __nv_bfloat16 bf16;

// ---------------- scratch (static __device__ — no allocations) ----------------
__device__ float g_s  [(size_t)NB * Tt * Tt];   // 256 MB fp32 scores
__device__ float g_att[MTOT * Dm];              // fp32 attention out
__device__ bf16  g_p  [(size_t)NB * Tt * Tt];   // 128 MB bf16 probabilities
__device__ bf16  g_yb [MTOT * Dm];              // LN out (bf16), reused LN1/LN2
__device__ bf16  g_qb [MTOT * Dm];
__device__ bf16  g_kb [MTOT * Dm];
__device__ bf16  g_vt [MTOT * Dm];              // vT: [Dm, MTOT]
__device__ bf16  g_hb [MTOT * Dm];
__device__ bf16  g_wb [5 * Dm * Dm];            // wqT, wkT, wvT, fc1w, fc2w (bf16)

// ================= helpers =================
__device__ __forceinline__ uint32_t smem_u32(const void* p) {
    uint32_t a;
    asm("{ .reg .u64 t; cvta.to.shared.u64 t, %1; cvt.u32.u64 %0, t; }" : "=r"(a) : "l"(p));
    return a;
}

#define CP_ASYNC16(dst, src) \
    asm volatile("cp.async.cg.shared.global [%0], [%1], 16;" :: "r"(dst), "l"(src))
#define CP_COMMIT() asm volatile("cp.async.commit_group;" ::: "memory")
#define CP_WAIT(n)  asm volatile("cp.async.wait_group %0;" :: "n"(n) : "memory")

#define MMA_BF16(d, a, b) \
    asm volatile("mma.sync.aligned.m16n8k16.row.col.f32.bf16.bf16.f32 " \
        "{%0,%1,%2,%3}, {%4,%5,%6,%7}, {%8,%9}, {%0,%1,%2,%3};" \
        : "+f"((d)[0]), "+f"((d)[1]), "+f"((d)[2]), "+f"((d)[3]) \
        : "r"((a)[0]), "r"((a)[1]), "r"((a)[2]), "r"((a)[3]), \
          "r"((b)[0]), "r"((b)[1]))

#define LDMX4(r0, r1, r2, r3, addr) \
    asm volatile("ldmatrix.sync.aligned.m8n8.x4.shared.b16 {%0,%1,%2,%3}, [%4];" \
        : "=r"(r0), "=r"(r1), "=r"(r2), "=r"(r3) : "r"(addr))

// swizzled BYTE offset inside a [128 rows x 128 bytes] tile
__device__ __forceinline__ int swb(int r, int cb) {
    return (r * 128 + cb) ^ ((r & 7) << 4);
}

// ================= bf16 mma.sync GEMM (ldmatrix fragments, reg double-buffer) ==========
// NT: C[M,N] = alpha * A[M,K] @ B[N,K]^T  (+bias)(relu)(+res)
// 128 threads (2x2 warps), CTA tile 128x128, WARP tile 64x64, K-chunk 64, 2-stage cp.async.
// Fragments double-buffered in registers: LDSM for kstep s+1 issued before MMAs of s.
template <bool OUTB, bool RELU>
__global__ __launch_bounds__(128, 2)
void gemm_bf16(const bf16* __restrict__ A, const bf16* __restrict__ B,
               const float* __restrict__ bias, const float* __restrict__ res,
               void* __restrict__ Cv, int K, int lda, int ldb, int ldc,
               size_t aS, size_t bS, size_t cS, float alpha)
{
    extern __shared__ char sm[];    // 2 stages x (A 16KB + B 16KB) = 64 KB
    const int tid  = threadIdx.x;
    const int w    = tid >> 5;
    const int lane = tid & 31;
    const int g    = lane >> 2;
    const int tig  = lane & 3;
    const int wm   = (w >> 1) * 64;   // warp M offset
    const int wn   = (w & 1) * 64;    // warp N offset
    const size_t bm = (size_t)blockIdx.y * 128;
    const size_t bn = (size_t)blockIdx.x * 128;
    const bf16* Ap = A + aS * blockIdx.z;
    const bf16* Bp = B + bS * blockIdx.z;

    // ldmatrix per-lane source coordinates
    const int lrA = (lane & 7) + ((lane >> 3) & 1) * 8;
    const int lcA = (lane >> 4) * 16;
    const int lrB = (lane & 7) + ((lane >> 4) & 1) * 8;
    const int lcB = ((lane >> 3) & 1) * 16;

    float acc[4][8][4];
    #pragma unroll
    for (int i = 0; i < 4; i++)
        #pragma unroll
        for (int j = 0; j < 8; j++)
            #pragma unroll
            for (int t = 0; t < 4; t++) acc[i][j][t] = 0.f;

    char* Ast[2] = { sm,         sm + 32768 };
    char* Bst[2] = { sm + 16384, sm + 32768 + 16384 };
    const int nch = K >> 6;

    // ---- prologue: stage 0 (128 threads, 8 chunks of 16B each per tile) ----
    #pragma unroll
    for (int i = 0; i < 8; i++) {
        const int fidx = i * 128 + tid;
        const int r  = fidx >> 3;
        const int c4 = fidx & 7;
        const int dst = r * 128 + ((c4 ^ (r & 7)) << 4);
        CP_ASYNC16(smem_u32(Ast[0] + dst), Ap + (bm + r) * (size_t)lda + c4 * 8);
        CP_ASYNC16(smem_u32(Bst[0] + dst), Bp + (bn + r) * (size_t)ldb + c4 * 8);
    }
    CP_COMMIT();

    uint32_t af[2][4][4];
    uint32_t bfr[2][8][2];

    for (int c = 0; c < nch; c++) {
        const int st = c & 1;
        if (c + 1 < nch) {
            const int k0 = (c + 1) << 6;
            char* An = Ast[st ^ 1];
            char* Bn = Bst[st ^ 1];
            #pragma unroll
            for (int i = 0; i < 8; i++) {
                const int fidx = i * 128 + tid;
                const int r  = fidx >> 3;
                const int c4 = fidx & 7;
                const int dst = r * 128 + ((c4 ^ (r & 7)) << 4);
                CP_ASYNC16(smem_u32(An + dst), Ap + (bm + r) * (size_t)lda + k0 + c4 * 8);
                CP_ASYNC16(smem_u32(Bn + dst), Bp + (bn + r) * (size_t)ldb + k0 + c4 * 8);
            }
            CP_COMMIT();
            CP_WAIT(1);
        } else {
            CP_WAIT(0);
        }
        __syncthreads();

        const char* Asm = Ast[st];
        const char* Bsm = Bst[st];

        // load k-step 0 fragments into buffer 0
        #pragma unroll
        for (int mt = 0; mt < 4; mt++) {
            const uint32_t aadr = smem_u32(Asm + swb(wm + mt * 16 + lrA, lcA));
            LDMX4(af[0][mt][0], af[0][mt][1], af[0][mt][2], af[0][mt][3], aadr);
        }
        #pragma unroll
        for (int np = 0; np < 4; np++) {
            const uint32_t badr = smem_u32(Bsm + swb(wn + np * 16 + lrB, lcB));
            LDMX4(bfr[0][np * 2][0], bfr[0][np * 2][1], bfr[0][np * 2 + 1][0], bfr[0][np * 2 + 1][1], badr);
        }

        #pragma unroll
        for (int ks = 0; ks < 4; ks++) {
            const int cur = ks & 1;
            if (ks < 3) {
                // prefetch k-step ks+1 fragments into the other buffer BEFORE MMAs
                const int nxt = cur ^ 1;
                const int cbn = (ks + 1) * 32;
                #pragma unroll
                for (int mt = 0; mt < 4; mt++) {
                    const uint32_t aadr = smem_u32(Asm + swb(wm + mt * 16 + lrA, cbn + lcA));
                    LDMX4(af[nxt][mt][0], af[nxt][mt][1], af[nxt][mt][2], af[nxt][mt][3], aadr);
                }
                #pragma unroll
                for (int np = 0; np < 4; np++) {
                    const uint32_t badr = smem_u32(Bsm + swb(wn + np * 16 + lrB, cbn + lcB));
                    LDMX4(bfr[nxt][np * 2][0], bfr[nxt][np * 2][1],
                          bfr[nxt][np * 2 + 1][0], bfr[nxt][np * 2 + 1][1], badr);
                }
            }
            #pragma unroll
            for (int mt = 0; mt < 4; mt++)
                #pragma unroll
                for (int nt = 0; nt < 8; nt++)
                    MMA_BF16(acc[mt][nt], af[cur][mt], bfr[cur][nt]);
        }
        __syncthreads();
    }

    // ---- epilogue ----
    float* Cf = (float*)Cv + cS * blockIdx.z;
    bf16*  Cb = (bf16*)Cv  + cS * blockIdx.z;
    const float* Rb = res ? res + cS * blockIdx.z : (const float*)0;
    #pragma unroll
    for (int mt = 0; mt < 4; mt++) {
        #pragma unroll
        for (int nt = 0; nt < 8; nt++) {
            const size_t row0 = bm + wm + mt * 16 + g;
            const int    col  = (int)bn + wn + nt * 8 + tig * 2;
            float b0 = 0.f, b1 = 0.f;
            if (bias) { b0 = bias[col]; b1 = bias[col + 1]; }
            #pragma unroll
            for (int h = 0; h < 2; h++) {
                const size_t r = row0 + h * 8;
                float v0 = acc[mt][nt][h * 2 + 0] * alpha + b0;
                float v1 = acc[mt][nt][h * 2 + 1] * alpha + b1;
                if (RELU) { v0 = fmaxf(v0, 0.f); v1 = fmaxf(v1, 0.f); }
                if (Rb) {
                    v0 += Rb[r * (size_t)ldc + col];
                    v1 += Rb[r * (size_t)ldc + col + 1];
                }
                if (OUTB) {
                    __nv_bfloat162 o;
                    o.x = __float2bfloat16(v0);
                    o.y = __float2bfloat16(v1);
                    *(__nv_bfloat162*)(Cb + r * (size_t)ldc + col) = o;
                } else {
                    float2 o = make_float2(v0, v1);
                    *(float2*)(Cf + r * (size_t)ldc + col) = o;
                }
            }
        }
    }
}

// ================= fused weight prep: 3x transpose+cvt, 2x cvt =================
__global__ void prep_weights(const float* __restrict__ wq, const float* __restrict__ wk,
                             const float* __restrict__ wv, const float* __restrict__ f1,
                             const float* __restrict__ f2, bf16* __restrict__ wb)
{
    const int z = blockIdx.z;
    const float* src = (z == 0) ? wq : (z == 1) ? wk : (z == 2) ? wv : (z == 3) ? f1 : f2;
    bf16* dst = wb + (size_t)z * Dm * Dm;
    const int c0 = blockIdx.x * 32, r0 = blockIdx.y * 32;
    const int tx = threadIdx.x & 31, ty = threadIdx.x >> 5;
    if (z < 3) {
        __shared__ float t[32][33];
        #pragma unroll
        for (int i = ty; i < 32; i += 8)
            t[i][tx] = src[(size_t)(r0 + i) * Dm + c0 + tx];
        __syncthreads();
        #pragma unroll
        for (int i = ty; i < 32; i += 8)
            dst[(size_t)(c0 + i) * Dm + r0 + tx] = __float2bfloat16(t[tx][i]);
    } else {
        #pragma unroll
        for (int i = ty; i < 32; i += 8)
            dst[(size_t)(r0 + i) * Dm + c0 + tx] = __float2bfloat16(src[(size_t)(r0 + i) * Dm + c0 + tx]);
    }
}

// ---------------- block reductions (256 threads) ----------------
__device__ __forceinline__ float blockSum(float v) {
    __shared__ float red[8];
    #pragma unroll
    for (int o = 16; o > 0; o >>= 1) v += __shfl_xor_sync(0xffffffffu, v, o);
    __syncthreads();
    if ((threadIdx.x & 31) == 0) red[threadIdx.x >> 5] = v;
    __syncthreads();
    float r = red[0];
    #pragma unroll
    for (int i = 1; i < 8; i++) r += red[i];
    return r;
}
__device__ __forceinline__ float blockMax(float v) {
    __shared__ float redm[8];
    #pragma unroll
    for (int o = 16; o > 0; o >>= 1) v = fmaxf(v, __shfl_xor_sync(0xffffffffu, v, o));
    __syncthreads();
    if ((threadIdx.x & 31) == 0) redm[threadIdx.x >> 5] = v;
    __syncthreads();
    float r = redm[0];
    #pragma unroll
    for (int i = 1; i < 8; i++) r = fmaxf(r, redm[i]);
    return r;
}

// ---------------- LayerNorm (faithful to buggy reference), bf16 out ----------------
__global__ void ln_kernel(const float* __restrict__ x, const float* __restrict__ g,
                          const float* __restrict__ b, bf16* __restrict__ out) {
    size_t row = blockIdx.x;
    const float* xr = x + row * Dm;
    int tid = threadIdx.x;
    float v0 = xr[tid], v1 = xr[tid + 256], v2 = xr[tid + 512];
    float mu = blockSum(v0 + v1 + v2) * (1.0f / Dm);
    float d0 = v0 - mu, d1 = v1 - mu, d2 = v2 - mu;
    float var = blockSum(d0 * d0 + d1 * d1 + d2 * d2) * (1.0f / (Dm - 1));
    float c = mu / sqrtf(var);           // reference's bug, reproduced exactly
    bf16* orow = out + row * Dm;
    orow[tid]       = __float2bfloat16((v0 - c) * g[tid]       + b[tid]);
    orow[tid + 256] = __float2bfloat16((v1 - c) * g[tid + 256] + b[tid + 256]);
    orow[tid + 512] = __float2bfloat16((v2 - c) * g[tid + 512] + b[tid + 512]);
}

// ---------------- row softmax over 4096: fp32 in, bf16 out ----------------
__global__ void softmax_kernel(const float* __restrict__ S, bf16* __restrict__ P) {
    size_t row = blockIdx.x;
    const float* sr = S + row * (size_t)Tt;
    bf16* pr = P + row * (size_t)Tt;
    int tid = threadIdx.x;
    float v[16];
    float m = -1e30f;
    #pragma unroll
    for (int i = 0; i < 16; i++) { v[i] = sr[tid + i * 256]; m = fmaxf(m, v[i]); }
    m = blockMax(m);
    float s = 0.f;
    #pragma unroll
    for (int i = 0; i < 16; i++) { v[i] = __expf(v[i] - m); s += v[i]; }
    s = blockSum(s);
    float inv = 1.0f / s;
    #pragma unroll
    for (int i = 0; i < 16; i++) pr[tid + i * 256] = __float2bfloat16(v[i] * inv);
}

// ---------------- launch ----------------
extern "C" void kernel_launch(void* const* d_in, const int* in_sizes, int n_in,
                              void* d_out, int out_size) {
    const float* x     = (const float*)d_in[0];
    const float* ln1_g = (const float*)d_in[1];
    const float* ln1_b = (const float*)d_in[2];
    const float* wq    = (const float*)d_in[3];
    const float* wk    = (const float*)d_in[4];
    const float* wv    = (const float*)d_in[5];
    const float* ln2_g = (const float*)d_in[6];
    const float* ln2_b = (const float*)d_in[7];
    const float* fc1_w = (const float*)d_in[8];
    const float* fc1_b = (const float*)d_in[9];
    const float* fc2_w = (const float*)d_in[10];
    const float* fc2_b = (const float*)d_in[11];
    float* out = (float*)d_out;

    float *s, *att;
    bf16 *p, *yb, *qb, *kb, *vt, *hb, *wb;
    cudaGetSymbolAddress((void**)&s,   g_s);
    cudaGetSymbolAddress((void**)&att, g_att);
    cudaGetSymbolAddress((void**)&p,   g_p);
    cudaGetSymbolAddress((void**)&yb,  g_yb);
    cudaGetSymbolAddress((void**)&qb,  g_qb);
    cudaGetSymbolAddress((void**)&kb,  g_kb);
    cudaGetSymbolAddress((void**)&vt,  g_vt);
    cudaGetSymbolAddress((void**)&hb,  g_hb);
    cudaGetSymbolAddress((void**)&wb,  g_wb);
    bf16* wqTb = wb;
    bf16* wkTb = wb + (size_t)Dm * Dm;
    bf16* wvTb = wb + 2 * (size_t)Dm * Dm;
    bf16* f1b  = wb + 3 * (size_t)Dm * Dm;
    bf16* f2b  = wb + 4 * (size_t)Dm * Dm;

    const size_t sTD = (size_t)Tt * Dm;
    const size_t sTT = (size_t)Tt * Tt;
    const float scale = 1.0f / sqrtf((float)Dm);
    const int SMEM = 64 * 1024;

    cudaFuncSetAttribute(gemm_bf16<true,  false>, cudaFuncAttributeMaxDynamicSharedMemorySize, SMEM);
    cudaFuncSetAttribute(gemm_bf16<false, false>, cudaFuncAttributeMaxDynamicSharedMemorySize, SMEM);
    cudaFuncSetAttribute(gemm_bf16<true,  true >, cudaFuncAttributeMaxDynamicSharedMemorySize, SMEM);

    // 0. fused weight prep (1 launch)
    dim3 gprep(Dm / 32, Dm / 32, 5);
    prep_weights<<<gprep, 256>>>(wq, wk, wv, fc1_w, fc2_w, wb);

    // 1. LN1 -> yb (bf16)
    ln_kernel<<<MTOT, 256>>>(x, ln1_g, ln1_b, yb);

    // 2. Q, K projections: [16384,768] @ [768,768]^T -> bf16
    dim3 gproj(Dm / 128, MTOT / 128, 1);
    gemm_bf16<true, false><<<gproj, 128, SMEM>>>(yb, wqTb, 0, 0, qb, Dm, Dm, Dm, Dm, 0, 0, 0, 1.0f);
    gemm_bf16<true, false><<<gproj, 128, SMEM>>>(yb, wkTb, 0, 0, kb, Dm, Dm, Dm, Dm, 0, 0, 0, 1.0f);

    // 2b. vT = Wv^T @ Y^T directly: C[768, 16384] = wvTb[768,768] @ yb[16384,768]^T
    dim3 gvt(MTOT / 128, Dm / 128, 1);
    gemm_bf16<true, false><<<gvt, 128, SMEM>>>(wvTb, yb, 0, 0, vt, Dm, Dm, Dm, MTOT, 0, 0, 0, 1.0f);

    // 3. scores = scale * Q @ K^T -> fp32, per batch
    dim3 gsc(Tt / 128, Tt / 128, NB);
    gemm_bf16<false, false><<<gsc, 128, SMEM>>>(qb, kb, 0, 0, s, Dm, Dm, Dm, Tt, sTD, sTD, sTT, scale);

    // 4. softmax rows: fp32 -> bf16 probabilities
    softmax_kernel<<<NB * Tt, 256>>>(s, p);

    // 5. att = P @ V = P @ (vT)^T -> fp32  (B = vt rows [Dm], ldb = MTOT, batch offset Tt)
    dim3 gav(Dm / 128, Tt / 128, NB);
    gemm_bf16<false, false><<<gav, 128, SMEM>>>(p, vt, 0, 0, att, Tt, Tt, MTOT, Dm, sTT, (size_t)Tt, sTD, 1.0f);

    // 6. LN2 -> yb (bf16)
    ln_kernel<<<MTOT, 256>>>(att, ln2_g, ln2_b, yb);

    // 7. MLP fc1 (+bias, ReLU) -> bf16 h
    gemm_bf16<true, true><<<gproj, 128, SMEM>>>(yb, f1b, fc1_b, 0, hb, Dm, Dm, Dm, Dm, 0, 0, 0, 1.0f);

    // 8. MLP fc2 (+bias, +residual x) -> fp32 out
    gemm_bf16<false, false><<<gproj, 128, SMEM>>>(hb, f2b, fc2_b, x, out, Dm, Dm, Dm, Dm, 0, 0, 0, 1.0f);
}